// round 12
// baseline (speedup 1.0000x reference)
#include <cuda_runtime.h>
#include <cstdint>

// CondConv3d via tf32 mma.sync implicit GEMM (tensor pipe; compute_103-safe).
// Round 12: R10 tile (TH=8, warp=row, M64xN32, 2 CTAs/SM) but W comes straight
// from gmem via __ldg (pair-packed layout: one LDG.64 = both B-frag regs).
// No W smem, no W staging, no per-chunk barriers -> only xT restage syncs.
//
// out[b] = s[b] * (conv3d(x[b], Wsum) + bias_sum)

#define B_ 8
#define CIN 32
#define COUT 32
#define DD 16
#define HH_ 64
#define WW 64

#define TH 8                        // output h rows per block
#define XROWS (TH + 2)              // 10
#define ROW_PITCH 68                // 64 data + 2 zero + 2 pad
#define XT_PITCH (XROWS * ROW_PITCH)   // 680; 680 % 32 == 8 (conflict-free)
#define XT_FLOATS (CIN * XT_PITCH)  // 21760 floats = 87040 B
#define W_TAP 1024                  // 32 o x 32 c (pair-packed), floats per tap
#define W_FLOATS (27 * W_TAP)       // 27648 (gmem)
#define SMEM_FLOATS XT_FLOATS

// g_wt pair-packed: [tap][o][kc][tig][half], half0 -> c = kc*8+tig,
// half1 -> c = kc*8+tig+4. Lane (g,tig) LDG.64 at (o)*32+kc*8+tig*2 gets
// exactly its m16n8k8 B-frag {b0,b1}.
__device__ float g_wt[W_FLOATS];
__device__ float g_bias[COUT];
__device__ float g_s[B_];

__device__ __forceinline__ float to_tf32(float v) {
    uint32_t u;
    asm("cvt.rna.tf32.f32 %0, %1;" : "=r"(u) : "f"(v));
    return __uint_as_float(u);
}

__global__ void prep_kernel(const float* __restrict__ weight,
                            const float* __restrict__ bias,
                            const float* __restrict__ rw) {
    int idx = blockIdx.x * 256 + threadIdx.x;
    if (idx < W_FLOATS) {
        int t  = idx / W_TAP;
        int rem = idx % W_TAP;
        int o  = rem >> 5;
        int ci = rem & 31;             // packed c index
        int kc   = ci >> 3;
        int r    = ci & 7;
        int tig  = r >> 1;
        int half = r & 1;
        int c = kc * 8 + tig + 4 * half;
        float v = 0.f;
        #pragma unroll
        for (int e = 0; e < 8; e++)
            v += weight[((e * 32 + o) * 32 + c) * 27 + t];
        g_wt[idx] = to_tf32(v);
    }
    if (blockIdx.x == 0) {
        int tid = threadIdx.x;
        if (tid < COUT) {
            float s = 0.f;
            #pragma unroll
            for (int e = 0; e < 8; e++) s += bias[e * COUT + tid];
            g_bias[tid] = s;
        } else if (tid < COUT + B_) {
            int b = tid - COUT;
            float s = 0.f;
            #pragma unroll
            for (int e = 0; e < 8; e++) s += rw[b * 8 + e];
            g_s[b] = s;
        }
    }
}

// ---- cp.async helpers ----
__device__ __forceinline__ void cp16_zfill(uint32_t saddr, const float* g, int srcsz) {
    asm volatile("cp.async.cg.shared.global [%0], [%1], 16, %2;"
                 :: "r"(saddr), "l"(g), "r"(srcsz));
}
__device__ __forceinline__ void cp_commit() { asm volatile("cp.async.commit_group;"); }
__device__ __forceinline__ void cp_wait0()  { asm volatile("cp.async.wait_group 0;"); }

__device__ __forceinline__ void mma_tf32(float* c, uint32_t a0, uint32_t a1,
                                         uint32_t a2, uint32_t a3,
                                         uint32_t b0, uint32_t b1) {
    asm volatile("mma.sync.aligned.m16n8k8.row.col.f32.tf32.tf32.f32 "
                 "{%0,%1,%2,%3}, {%4,%5,%6,%7}, {%8,%9}, {%0,%1,%2,%3};"
                 : "+f"(c[0]), "+f"(c[1]), "+f"(c[2]), "+f"(c[3])
                 : "r"(a0), "r"(a1), "r"(a2), "r"(a3), "r"(b0), "r"(b1));
}

extern __shared__ float smem[];

__global__ __launch_bounds__(256, 2) void conv_kernel(const float* __restrict__ x,
                                                      float* __restrict__ out) {
    const int tid  = threadIdx.x;
    const int wid  = tid >> 5;         // warp = one output h row (0..7)
    const int lane = tid & 31;
    const int g    = lane >> 2;        // fragment groupID
    const int tig  = lane & 3;         // fragment threadID-in-group

    const int htile = blockIdx.x;      // 8 h rows each
    const int d     = blockIdx.y;
    const int b     = blockIdx.z;
    const int h0    = htile * TH;

    const float* __restrict__ xb = x + (size_t)b * CIN * DD * HH_ * WW;
    const uint32_t smem_u = (uint32_t)__cvta_generic_to_shared(smem);

    // ---- init permanent zero slots (ww3 = 64..67 of every row) ----
    for (int i = tid; i < CIN * XROWS * 4; i += 256) {
        int c = i / (XROWS * 4);
        int r = (i / 4) % XROWS;
        int z = i & 3;
        smem[c * XT_PITCH + r * ROW_PITCH + 64 + z] = 0.f;
    }

    // ---- xT staging: 32c x 10 rows x 16 chunks = 5120 cp16 (20/thread) ----
    const int sc = tid >> 3;           // c 0..31
    const int s8 = tid & 7;
    auto stage_x = [&](int dz) {
        int gd = d + dz - 1;
        bool dok = (gd >= 0) && (gd < DD);
        const float* base = xb + ((size_t)sc * DD + (dok ? gd : 0)) * HH_ * WW;
        #pragma unroll
        for (int j = 0; j < 20; j++) {
            int slot = s8 + 8 * j;     // 0..159
            int hh2  = slot >> 4;      // row 0..9
            int q    = slot & 15;      // 4-float chunk
            int gh = h0 + hh2 - 1;
            bool ok = dok && (gh >= 0) && (gh < HH_);
            uint32_t dst = smem_u +
                (sc * XT_PITCH + hh2 * ROW_PITCH + q * 4) * 4;
            cp16_zfill(dst, base + (ok ? gh : 0) * WW + q * 4, ok ? 16 : 0);
        }
    };

    // ---- accumulators: C[mi][ni][4] (M64 x N32 per warp) ----
    float acc[4][4][4];
    #pragma unroll
    for (int mi = 0; mi < 4; mi++)
        #pragma unroll
        for (int ni = 0; ni < 4; ni++)
            #pragma unroll
            for (int r = 0; r < 4; r++) acc[mi][ni][r] = 0.f;

    const uint32_t* xtu = reinterpret_cast<const uint32_t*>(smem);

    // ---- prologue ----
    stage_x(0);
    cp_commit();
    cp_wait0();
    __syncthreads();

    // per-lane W base: + tap*1024 + (ni*8)*32 + kc*8 later
    const float2* __restrict__ wbase =
        reinterpret_cast<const float2*>(g_wt) + (g * 32 + tig * 2) / 2;

    #pragma unroll 1
    for (int dz = 0; dz < 3; dz++) {
        #pragma unroll 1
        for (int kh = 0; kh < 3; kh++) {
            const int hh2 = wid + kh;                    // 0..9
            const uint32_t* xrow = xtu + hh2 * ROW_PITCH;
            #pragma unroll
            for (int kw = 0; kw < 3; kw++) {
                const int kwm1 = kw - 1;
                const int tap = (dz * 3 + kh) * 3 + kw;
                const float2* wtap = wbase + tap * (W_TAP / 2);
                #pragma unroll
                for (int kc = 0; kc < 4; kc++) {
                    const int c0 = kc * 8 + tig;
                    // B fragments: one LDG.64 per ni (pair-packed layout)
                    uint32_t b0[4], b1[4];
                    #pragma unroll
                    for (int ni = 0; ni < 4; ni++) {
                        float2 bb = __ldg(wtap + (ni * 8 * 32 + kc * 8) / 2);
                        b0[ni] = __float_as_uint(bb.x);
                        b1[ni] = __float_as_uint(bb.y);
                    }
                    #pragma unroll
                    for (int mi = 0; mi < 4; mi++) {
                        int win = mi * 16 + g + kwm1;
                        int r0 = (win < 0) ? 65 : win;   // left halo -> zero slot
                        int r1 = win + 8;                // 64 -> zero slot
                        const uint32_t* xc = xrow + c0 * XT_PITCH;
                        uint32_t a0 = xc[r0];
                        uint32_t a1 = xc[r1];
                        uint32_t a2 = xc[r0 + 4 * XT_PITCH];
                        uint32_t a3 = xc[r1 + 4 * XT_PITCH];
                        #pragma unroll
                        for (int ni = 0; ni < 4; ni++)
                            mma_tf32(acc[mi][ni], a0, a1, a2, a3, b0[ni], b1[ni]);
                    }
                }
            }
        }
        // ---- dz boundary: restage xT (only syncs in the mainloop) ----
        if (dz < 2) {
            __syncthreads();           // all reads of xT done before overwrite
            stage_x(dz + 1);
            cp_commit();
            cp_wait0();
            __syncthreads();
        }
    }

    // ---- epilogue: out[b][o][d][h][w] = s*(acc + bias[o]) ----
    const float sb = g_s[b];
    const int h = h0 + wid;
    #pragma unroll
    for (int ni = 0; ni < 4; ni++) {
        const int o0 = ni * 8 + 2 * tig;
        const float bs0 = g_bias[o0];
        const float bs1 = g_bias[o0 + 1];
        float* p0 = out + (((size_t)(b * COUT + o0) * DD + d) * HH_ + h) * WW;
        float* p1 = out + (((size_t)(b * COUT + o0 + 1) * DD + d) * HH_ + h) * WW;
        #pragma unroll
        for (int mi = 0; mi < 4; mi++) {
            const int w = mi * 16 + g;
            p0[w]     = sb * (acc[mi][ni][0] + bs0);
            p1[w]     = sb * (acc[mi][ni][1] + bs1);
            p0[w + 8] = sb * (acc[mi][ni][2] + bs0);
            p1[w + 8] = sb * (acc[mi][ni][3] + bs1);
        }
    }
}

extern "C" void kernel_launch(void* const* d_in, const int* in_sizes, int n_in,
                              void* d_out, int out_size) {
    // x: 16777216, rw: 64, weight: 221184, bias: 256
    const float *x = nullptr, *rw = nullptr, *wt = nullptr, *bi = nullptr;
    for (int i = 0; i < n_in; i++) {
        if (in_sizes[i] == 16777216)     x  = (const float*)d_in[i];
        else if (in_sizes[i] == 221184)  wt = (const float*)d_in[i];
        else if (in_sizes[i] == 256)     bi = (const float*)d_in[i];
        else if (in_sizes[i] == 64)      rw = (const float*)d_in[i];
    }
    float* out = (float*)d_out;

    cudaFuncSetAttribute(conv_kernel,
                         cudaFuncAttributeMaxDynamicSharedMemorySize,
                         SMEM_FLOATS * 4);

    prep_kernel<<<(W_FLOATS + 255) / 256, 256>>>(wt, bi, rw);

    dim3 grid(HH_ / TH, DD, B_);   // (8, 16, 8) = 1024 blocks
    conv_kernel<<<grid, 256, SMEM_FLOATS * 4>>>(x, out);
}

// round 13
// speedup vs baseline: 1.8915x; 1.8915x over previous
#include <cuda_runtime.h>
#include <cstdint>

// CondConv3d via tf32 mma.sync implicit GEMM (tensor pipe; compute_103-safe).
// Round 13: R10 structure, but B fragments frag-packed in smem so each lane
// loads its 8 B-regs per (tap,kc) with 2x LDS.128 (lane-contiguous, 4-cyc
// wavefronts) instead of 8x LDS.64. W chunk = 12KB; smem 111.6KB, 2 CTAs/SM.
//
// out[b] = s[b] * (conv3d(x[b], Wsum) + bias_sum)

#define B_ 8
#define CIN 32
#define COUT 32
#define DD 16
#define HH_ 64
#define WW 64

#define TH 8                        // output h rows per block
#define XROWS (TH + 2)              // 10
#define ROW_PITCH 68                // 64 data + 2 zero + 2 pad
#define XT_PITCH (XROWS * ROW_PITCH)   // 680; 680 % 32 == 8 (conflict-free)
#define XT_FLOATS (CIN * XT_PITCH)  // 21760
#define W_TAP 1024                  // frag-packed: 4kc x 2ch x 32lane x 4 floats
#define W_CHUNK (3 * W_TAP)         // 3072 floats per (dz,kh) chunk (12KB)
#define W_FLOATS (27 * W_TAP)       // 27648 (gmem)
#define OFF_XT 0
#define OFF_W XT_FLOATS
#define SMEM_FLOATS (XT_FLOATS + 2 * W_CHUNK)   // 27904 floats = 111616 B

// g_wt frag-packed: idx = (((tap*4+kc)*2+ch)*32 + lane)*4 + j
//   lane = g*4+tig; ni = ch*2 + (j>>1); half = j&1
//   o = ni*8+g; c = kc*8 + tig + 4*half
__device__ float g_wt[W_FLOATS];
__device__ float g_bias[COUT];
__device__ float g_s[B_];

__device__ __forceinline__ float to_tf32(float v) {
    uint32_t u;
    asm("cvt.rna.tf32.f32 %0, %1;" : "=r"(u) : "f"(v));
    return __uint_as_float(u);
}

__global__ void prep_kernel(const float* __restrict__ weight,
                            const float* __restrict__ bias,
                            const float* __restrict__ rw) {
    int idx = blockIdx.x * 256 + threadIdx.x;
    if (idx < W_FLOATS) {
        int tap  = idx >> 10;
        int kc   = (idx >> 8) & 3;
        int ch   = (idx >> 7) & 1;
        int lane = (idx >> 2) & 31;
        int j    = idx & 3;
        int g    = lane >> 2;
        int tig  = lane & 3;
        int ni   = ch * 2 + (j >> 1);
        int half = j & 1;
        int o = ni * 8 + g;
        int c = kc * 8 + tig + 4 * half;
        float v = 0.f;
        #pragma unroll
        for (int e = 0; e < 8; e++)
            v += weight[((e * 32 + o) * 32 + c) * 27 + tap];
        g_wt[idx] = to_tf32(v);
    }
    if (blockIdx.x == 0) {
        int tid = threadIdx.x;
        if (tid < COUT) {
            float s = 0.f;
            #pragma unroll
            for (int e = 0; e < 8; e++) s += bias[e * COUT + tid];
            g_bias[tid] = s;
        } else if (tid < COUT + B_) {
            int b = tid - COUT;
            float s = 0.f;
            #pragma unroll
            for (int e = 0; e < 8; e++) s += rw[b * 8 + e];
            g_s[b] = s;
        }
    }
}

// ---- cp.async helpers ----
__device__ __forceinline__ void cp16_zfill(uint32_t saddr, const float* g, int srcsz) {
    asm volatile("cp.async.cg.shared.global [%0], [%1], 16, %2;"
                 :: "r"(saddr), "l"(g), "r"(srcsz));
}
__device__ __forceinline__ void cp16(uint32_t saddr, const float* g) {
    asm volatile("cp.async.cg.shared.global [%0], [%1], 16;"
                 :: "r"(saddr), "l"(g));
}
__device__ __forceinline__ void cp_commit() { asm volatile("cp.async.commit_group;"); }
__device__ __forceinline__ void cp_wait0()  { asm volatile("cp.async.wait_group 0;"); }

__device__ __forceinline__ void mma_tf32(float* c, uint32_t a0, uint32_t a1,
                                         uint32_t a2, uint32_t a3,
                                         uint32_t b0, uint32_t b1) {
    asm volatile("mma.sync.aligned.m16n8k8.row.col.f32.tf32.tf32.f32 "
                 "{%0,%1,%2,%3}, {%4,%5,%6,%7}, {%8,%9}, {%0,%1,%2,%3};"
                 : "+f"(c[0]), "+f"(c[1]), "+f"(c[2]), "+f"(c[3])
                 : "r"(a0), "r"(a1), "r"(a2), "r"(a3), "r"(b0), "r"(b1));
}

extern __shared__ float smem[];

__global__ __launch_bounds__(256, 2) void conv_kernel(const float* __restrict__ x,
                                                      float* __restrict__ out) {
    const int tid  = threadIdx.x;
    const int wid  = tid >> 5;         // warp = one output h row (0..7)
    const int lane = tid & 31;
    const int g    = lane >> 2;        // fragment groupID
    const int tig  = lane & 3;         // fragment threadID-in-group

    const int htile = blockIdx.x;      // 8 h rows each
    const int d     = blockIdx.y;
    const int b     = blockIdx.z;
    const int h0    = htile * TH;

    const float* __restrict__ xb = x + (size_t)b * CIN * DD * HH_ * WW;
    const uint32_t smem_u = (uint32_t)__cvta_generic_to_shared(smem);

    // ---- init permanent zero slots (ww3 = 64..67 of every row) ----
    for (int i = tid; i < CIN * XROWS * 4; i += 256) {
        int c = i / (XROWS * 4);
        int r = (i / 4) % XROWS;
        int z = i & 3;
        smem[OFF_XT + c * XT_PITCH + r * ROW_PITCH + 64 + z] = 0.f;
    }

    // ---- xT staging: 32c x 10 rows x 16 chunks = 5120 cp16 (20/thread) ----
    const int sc = tid >> 3;           // c 0..31
    const int s8 = tid & 7;
    auto stage_x = [&](int dz) {
        int gd = d + dz - 1;
        bool dok = (gd >= 0) && (gd < DD);
        const float* base = xb + ((size_t)sc * DD + (dok ? gd : 0)) * HH_ * WW;
        #pragma unroll
        for (int j = 0; j < 20; j++) {
            int slot = s8 + 8 * j;     // 0..159
            int hh2  = slot >> 4;      // row 0..9
            int q    = slot & 15;      // 4-float chunk
            int gh = h0 + hh2 - 1;
            bool ok = dok && (gh >= 0) && (gh < HH_);
            uint32_t dst = smem_u +
                (OFF_XT + sc * XT_PITCH + hh2 * ROW_PITCH + q * 4) * 4;
            cp16_zfill(dst, base + (ok ? gh : 0) * WW + q * 4, ok ? 16 : 0);
        }
    };
    // ---- W chunk staging: 768 float4 (3/thread) into buffer bf ----
    auto stage_w = [&](int chunk, int bf) {
        const float* src = g_wt + chunk * W_CHUNK;
        uint32_t dst = smem_u + (OFF_W + bf * W_CHUNK) * 4;
        #pragma unroll
        for (int k = 0; k < 3; k++) {
            int idx = tid + 256 * k;
            if (idx < W_CHUNK / 4)
                cp16(dst + idx * 16, src + idx * 4);
        }
    };

    // ---- accumulators: C[mi][ni][4] (M64 x N32 per warp) ----
    float acc[4][4][4];
    #pragma unroll
    for (int mi = 0; mi < 4; mi++)
        #pragma unroll
        for (int ni = 0; ni < 4; ni++)
            #pragma unroll
            for (int r = 0; r < 4; r++) acc[mi][ni][r] = 0.f;

    const uint32_t* xtu = reinterpret_cast<const uint32_t*>(smem + OFF_XT);

    // ---- prologue ----
    stage_w(0, 0);
    stage_x(0);
    cp_commit();
    cp_wait0();
    __syncthreads();

    #pragma unroll 1
    for (int chunk = 0; chunk < 9; chunk++) {
        const int dz = chunk / 3;
        const int kh = chunk % 3;
        const int bf = chunk & 1;

        // prefetch next W chunk into the other buffer (overlaps compute)
        if (chunk < 8) {
            stage_w(chunk + 1, bf ^ 1);
            cp_commit();
        }

        // ---- compute this (dz,kh) chunk: 3 kw x 4 kc x 16 MMAs ----
        const int hh2 = wid + kh;                       // 0..9
        const uint32_t* xrow = xtu + hh2 * ROW_PITCH;
        // lane-contiguous frag-packed W: base of this buffer + lane*4 floats
        const float4* __restrict__ wlane = reinterpret_cast<const float4*>(
            smem + OFF_W + bf * W_CHUNK) + lane;
        #pragma unroll
        for (int kw = 0; kw < 3; kw++) {
            const int kwm1 = kw - 1;
            const float4* wtap = wlane + kw * (W_TAP / 4);
            #pragma unroll
            for (int kc = 0; kc < 4; kc++) {
                const int c0 = kc * 8 + tig;
                // B fragments: 2x LDS.128 (ni0,ni1 | ni2,ni3)
                float4 bb0 = wtap[kc * 64];        // + (kc*2+0)*32 float4
                float4 bb1 = wtap[kc * 64 + 32];   // + (kc*2+1)*32 float4
                uint32_t b0[4], b1[4];
                b0[0] = __float_as_uint(bb0.x); b1[0] = __float_as_uint(bb0.y);
                b0[1] = __float_as_uint(bb0.z); b1[1] = __float_as_uint(bb0.w);
                b0[2] = __float_as_uint(bb1.x); b1[2] = __float_as_uint(bb1.y);
                b0[3] = __float_as_uint(bb1.z); b1[3] = __float_as_uint(bb1.w);
                #pragma unroll
                for (int mi = 0; mi < 4; mi++) {
                    int win = mi * 16 + g + kwm1;
                    int r0 = (win < 0) ? 65 : win;      // left halo -> zero slot
                    int r1 = win + 8;                   // 64 -> zero slot
                    const uint32_t* xc = xrow + c0 * XT_PITCH;
                    uint32_t a0 = xc[r0];
                    uint32_t a1 = xc[r1];
                    uint32_t a2 = xc[r0 + 4 * XT_PITCH];
                    uint32_t a3 = xc[r1 + 4 * XT_PITCH];
                    #pragma unroll
                    for (int ni = 0; ni < 4; ni++)
                        mma_tf32(acc[mi][ni], a0, a1, a2, a3, b0[ni], b1[ni]);
                }
            }
        }

        // ---- chunk boundary: make prefetched W visible; restage xT at dz edge ----
        if (kh == 2 && dz < 2) {
            __syncthreads();           // all reads of xT done before overwrite
            stage_x(dz + 1);
            cp_commit();
            cp_wait0();                // waits xT + pending W prefetch
            __syncthreads();
        } else if (chunk < 8) {
            cp_wait0();                // W prefetch complete (thread-local)
            __syncthreads();           // visible to all warps
        }
    }

    // ---- epilogue: out[b][o][d][h][w] = s*(acc + bias[o]) ----
    const float sb = g_s[b];
    const int h = h0 + wid;
    #pragma unroll
    for (int ni = 0; ni < 4; ni++) {
        const int o0 = ni * 8 + 2 * tig;
        const float bs0 = g_bias[o0];
        const float bs1 = g_bias[o0 + 1];
        float* p0 = out + (((size_t)(b * COUT + o0) * DD + d) * HH_ + h) * WW;
        float* p1 = out + (((size_t)(b * COUT + o0 + 1) * DD + d) * HH_ + h) * WW;
        #pragma unroll
        for (int mi = 0; mi < 4; mi++) {
            const int w = mi * 16 + g;
            p0[w]     = sb * (acc[mi][ni][0] + bs0);
            p1[w]     = sb * (acc[mi][ni][1] + bs1);
            p0[w + 8] = sb * (acc[mi][ni][2] + bs0);
            p1[w + 8] = sb * (acc[mi][ni][3] + bs1);
        }
    }
}

extern "C" void kernel_launch(void* const* d_in, const int* in_sizes, int n_in,
                              void* d_out, int out_size) {
    // x: 16777216, rw: 64, weight: 221184, bias: 256
    const float *x = nullptr, *rw = nullptr, *wt = nullptr, *bi = nullptr;
    for (int i = 0; i < n_in; i++) {
        if (in_sizes[i] == 16777216)     x  = (const float*)d_in[i];
        else if (in_sizes[i] == 221184)  wt = (const float*)d_in[i];
        else if (in_sizes[i] == 256)     bi = (const float*)d_in[i];
        else if (in_sizes[i] == 64)      rw = (const float*)d_in[i];
    }
    float* out = (float*)d_out;

    cudaFuncSetAttribute(conv_kernel,
                         cudaFuncAttributeMaxDynamicSharedMemorySize,
                         SMEM_FLOATS * 4);

    prep_kernel<<<(W_FLOATS + 255) / 256, 256>>>(wt, bi, rw);

    dim3 grid(HH_ / TH, DD, B_);   // (8, 16, 8) = 1024 blocks
    conv_kernel<<<grid, 256, SMEM_FLOATS * 4>>>(x, out);
}

// round 14
// speedup vs baseline: 2.0667x; 1.0926x over previous
#include <cuda_runtime.h>
#include <cstdint>

// CondConv3d via tf32 mma.sync implicit GEMM (tensor pipe; compute_103-safe).
// Round 14: fully pipelined 12-stage loop (3 dz x 4 kc). Each stage's xT
// quarter (8 channels) and W slice (9 taps, 8 c) are double-buffered and
// prefetched two stages ahead -> no blocking restage anywhere in mainloop.
// Per-warp tile M64xN32 (R10's proven ratio). smem 71KB, 2 CTAs/SM.
//
// out[b] = s[b] * (conv3d(x[b], Wsum) + bias_sum)

#define B_ 8
#define CIN 32
#define COUT 32
#define DD 16
#define HH_ 64
#define WW 64

#define TH 8                        // output h rows per block
#define XROWS (TH + 2)              // 10
#define ROW_PITCH 68                // 64 data + 2 zero + 2 pad
#define CQ_PITCH (XROWS * ROW_PITCH)   // 680 floats per channel
#define XQ_FLOATS (8 * CQ_PITCH)    // 5440 floats per xT quarter (8 c)
#define WPC8 12                     // 8 c + 4 pad (banks 12r+tig distinct)
#define W_SLICE (9 * COUT * WPC8)   // 3456 floats per (dz,kc) W slice
#define W_FLOATS (12 * W_SLICE)     // 41472 (gmem, [dz][kc][t9][o][12])
#define OFF_XT 0
#define OFF_W (2 * XQ_FLOATS)       // 10880
#define SMEM_FLOATS (2 * XQ_FLOATS + 2 * W_SLICE)  // 17792 floats = 71168 B

__device__ float g_wt[W_FLOATS];
__device__ float g_bias[COUT];
__device__ float g_s[B_];

__device__ __forceinline__ float to_tf32(float v) {
    uint32_t u;
    asm("cvt.rna.tf32.f32 %0, %1;" : "=r"(u) : "f"(v));
    return __uint_as_float(u);
}

__global__ void prep_kernel(const float* __restrict__ weight,
                            const float* __restrict__ bias,
                            const float* __restrict__ rw) {
    int idx = blockIdx.x * 256 + threadIdx.x;
    if (idx < W_FLOATS) {
        int dz  = idx / (4 * W_SLICE);
        int rem = idx % (4 * W_SLICE);
        int kc  = rem / W_SLICE;
        int r2  = rem % W_SLICE;
        int t9  = r2 / (COUT * WPC8);
        int r3  = r2 % (COUT * WPC8);
        int o   = r3 / WPC8;
        int cl  = r3 % WPC8;
        float v = 0.f;
        if (cl < 8) {
            int c = kc * 8 + cl;
            int tap = dz * 9 + t9;
            #pragma unroll
            for (int e = 0; e < 8; e++)
                v += weight[((e * 32 + o) * 32 + c) * 27 + tap];
            v = to_tf32(v);
        }
        g_wt[idx] = v;
    }
    if (blockIdx.x == 0) {
        int tid = threadIdx.x;
        if (tid < COUT) {
            float s = 0.f;
            #pragma unroll
            for (int e = 0; e < 8; e++) s += bias[e * COUT + tid];
            g_bias[tid] = s;
        } else if (tid < COUT + B_) {
            int b = tid - COUT;
            float s = 0.f;
            #pragma unroll
            for (int e = 0; e < 8; e++) s += rw[b * 8 + e];
            g_s[b] = s;
        }
    }
}

// ---- cp.async helpers ----
__device__ __forceinline__ void cp16_zfill(uint32_t saddr, const float* g, int srcsz) {
    asm volatile("cp.async.cg.shared.global [%0], [%1], 16, %2;"
                 :: "r"(saddr), "l"(g), "r"(srcsz));
}
__device__ __forceinline__ void cp16(uint32_t saddr, const float* g) {
    asm volatile("cp.async.cg.shared.global [%0], [%1], 16;"
                 :: "r"(saddr), "l"(g));
}
__device__ __forceinline__ void cp_commit() { asm volatile("cp.async.commit_group;"); }
__device__ __forceinline__ void cp_wait1()  { asm volatile("cp.async.wait_group 1;"); }
__device__ __forceinline__ void cp_wait0()  { asm volatile("cp.async.wait_group 0;"); }

__device__ __forceinline__ void mma_tf32(float* c, uint32_t a0, uint32_t a1,
                                         uint32_t a2, uint32_t a3,
                                         uint32_t b0, uint32_t b1) {
    asm volatile("mma.sync.aligned.m16n8k8.row.col.f32.tf32.tf32.f32 "
                 "{%0,%1,%2,%3}, {%4,%5,%6,%7}, {%8,%9}, {%0,%1,%2,%3};"
                 : "+f"(c[0]), "+f"(c[1]), "+f"(c[2]), "+f"(c[3])
                 : "r"(a0), "r"(a1), "r"(a2), "r"(a3), "r"(b0), "r"(b1));
}

extern __shared__ float smem[];

__global__ __launch_bounds__(256, 2) void conv_kernel(const float* __restrict__ x,
                                                      float* __restrict__ out) {
    const int tid  = threadIdx.x;
    const int wid  = tid >> 5;         // warp = one output h row (0..7)
    const int lane = tid & 31;
    const int g    = lane >> 2;        // fragment groupID
    const int tig  = lane & 3;         // fragment threadID-in-group

    const int htile = blockIdx.x;      // 8 h rows each
    const int d     = blockIdx.y;
    const int b     = blockIdx.z;
    const int h0    = htile * TH;

    const float* __restrict__ xb = x + (size_t)b * CIN * DD * HH_ * WW;
    const uint32_t smem_u = (uint32_t)__cvta_generic_to_shared(smem);

    // ---- init permanent zero slots (cols 64..67) in BOTH xT buffers ----
    for (int i = tid; i < 2 * 8 * XROWS * 4; i += 256) {
        int bf = i / (8 * XROWS * 4);
        int rem = i % (8 * XROWS * 4);
        int cl = rem / (XROWS * 4);
        int r  = (rem / 4) % XROWS;
        int z  = rem & 3;
        smem[OFF_XT + bf * XQ_FLOATS + cl * CQ_PITCH + r * ROW_PITCH + 64 + z] = 0.f;
    }

    // ---- stage one (dz,kc) xT quarter: 8c x 10 rows x 16 chunks = 1280 cp16 ----
    const int sc  = tid >> 5;          // c-local 0..7 (warp per channel)
    const int s32 = tid & 31;
    auto stage_xq = [&](int s, int bf) {
        int dz = s >> 2, kc = s & 3;
        int gd = d + dz - 1;
        bool dok = (gd >= 0) && (gd < DD);
        const float* base =
            xb + ((size_t)(kc * 8 + sc) * DD + (dok ? gd : 0)) * HH_ * WW;
        uint32_t dst0 = smem_u + (OFF_XT + bf * XQ_FLOATS + sc * CQ_PITCH) * 4;
        #pragma unroll
        for (int j = 0; j < 5; j++) {
            int slot = s32 + 32 * j;   // 0..159
            int row  = slot >> 4;      // 0..9
            int q    = slot & 15;
            int gh = h0 + row - 1;
            bool ok = dok && (gh >= 0) && (gh < HH_);
            cp16_zfill(dst0 + (row * ROW_PITCH + q * 4) * 4,
                       base + (ok ? gh : 0) * WW + q * 4, ok ? 16 : 0);
        }
    };
    // ---- stage one (dz,kc) W slice: 864 float4 ----
    auto stage_w = [&](int s, int bf) {
        const float* src = g_wt + s * W_SLICE;
        uint32_t dst = smem_u + (OFF_W + bf * W_SLICE) * 4;
        #pragma unroll
        for (int k = 0; k < 4; k++) {
            int idx = tid + 256 * k;
            if (idx < W_SLICE / 4)
                cp16(dst + idx * 16, src + idx * 4);
        }
    };

    // ---- accumulators: C[mi][ni][4] (M64 x N32 per warp) ----
    float acc[4][4][4];
    #pragma unroll
    for (int mi = 0; mi < 4; mi++)
        #pragma unroll
        for (int ni = 0; ni < 4; ni++)
            #pragma unroll
            for (int r = 0; r < 4; r++) acc[mi][ni][r] = 0.f;

    // ---- prologue: stage s=0 (group0) and s=1 (group1) ----
    stage_xq(0, 0); stage_w(0, 0); cp_commit();
    stage_xq(1, 1); stage_w(1, 1); cp_commit();
    cp_wait1();                        // group0 (stage 0) complete
    __syncthreads();

    #pragma unroll 1
    for (int s = 0; s < 12; s++) {
        const int bf = s & 1;
        const uint32_t* xbuf = reinterpret_cast<const uint32_t*>(
            smem + OFF_XT + bf * XQ_FLOATS);
        const uint32_t* wbuf = reinterpret_cast<const uint32_t*>(
            smem + OFF_W + bf * W_SLICE);

        // ---- compute stage s: 9 taps x 16 MMAs ----
        #pragma unroll
        for (int kh = 0; kh < 3; kh++) {
            const uint32_t* xrow = xbuf + (wid + kh) * ROW_PITCH + tig * CQ_PITCH;
            #pragma unroll
            for (int kw = 0; kw < 3; kw++) {
                const int kwm1 = kw - 1;
                const uint32_t* wtap = wbuf + (kh * 3 + kw) * (COUT * WPC8);
                uint32_t b0[4], b1[4];
                #pragma unroll
                for (int ni = 0; ni < 4; ni++) {
                    const uint32_t* wb = wtap + (ni * 8 + g) * WPC8 + tig;
                    b0[ni] = wb[0];
                    b1[ni] = wb[4];
                }
                #pragma unroll
                for (int mi = 0; mi < 4; mi++) {
                    int win = mi * 16 + g + kwm1;
                    int r0 = (win < 0) ? 65 : win;      // left halo -> zero slot
                    int r1 = win + 8;                   // 64 -> zero slot
                    uint32_t a0 = xrow[r0];
                    uint32_t a1 = xrow[r1];
                    uint32_t a2 = xrow[r0 + 4 * CQ_PITCH];
                    uint32_t a3 = xrow[r1 + 4 * CQ_PITCH];
                    #pragma unroll
                    for (int ni = 0; ni < 4; ni++)
                        mma_tf32(acc[mi][ni], a0, a1, a2, a3, b0[ni], b1[ni]);
                }
            }
        }

        // ---- pipeline advance ----
        if (s <= 9) {
            __syncthreads();           // all warps done reading buffer bf
            stage_xq(s + 2, bf);       // refill bf for stage s+2
            stage_w(s + 2, bf);
            cp_commit();
            cp_wait1();                // stage s+1's group complete
            __syncthreads();
        } else if (s == 10) {
            cp_wait0();                // stage 11's group complete
            __syncthreads();
        }
    }

    // ---- epilogue: out[b][o][d][h][w] = s*(acc + bias[o]) ----
    const float sb = g_s[b];
    const int h = h0 + wid;
    #pragma unroll
    for (int ni = 0; ni < 4; ni++) {
        const int o0 = ni * 8 + 2 * tig;
        const float bs0 = g_bias[o0];
        const float bs1 = g_bias[o0 + 1];
        float* p0 = out + (((size_t)(b * COUT + o0) * DD + d) * HH_ + h) * WW;
        float* p1 = out + (((size_t)(b * COUT + o0 + 1) * DD + d) * HH_ + h) * WW;
        #pragma unroll
        for (int mi = 0; mi < 4; mi++) {
            const int w = mi * 16 + g;
            p0[w]     = sb * (acc[mi][ni][0] + bs0);
            p1[w]     = sb * (acc[mi][ni][1] + bs1);
            p0[w + 8] = sb * (acc[mi][ni][2] + bs0);
            p1[w + 8] = sb * (acc[mi][ni][3] + bs1);
        }
    }
}

extern "C" void kernel_launch(void* const* d_in, const int* in_sizes, int n_in,
                              void* d_out, int out_size) {
    // x: 16777216, rw: 64, weight: 221184, bias: 256
    const float *x = nullptr, *rw = nullptr, *wt = nullptr, *bi = nullptr;
    for (int i = 0; i < n_in; i++) {
        if (in_sizes[i] == 16777216)     x  = (const float*)d_in[i];
        else if (in_sizes[i] == 221184)  wt = (const float*)d_in[i];
        else if (in_sizes[i] == 256)     bi = (const float*)d_in[i];
        else if (in_sizes[i] == 64)      rw = (const float*)d_in[i];
    }
    float* out = (float*)d_out;

    cudaFuncSetAttribute(conv_kernel,
                         cudaFuncAttributeMaxDynamicSharedMemorySize,
                         SMEM_FLOATS * 4);

    prep_kernel<<<(W_FLOATS + 255) / 256, 256>>>(wt, bi, rw);

    dim3 grid(HH_ / TH, DD, B_);   // (8, 16, 8) = 1024 blocks
    conv_kernel<<<grid, 256, SMEM_FLOATS * 4>>>(x, out);
}